// round 1
// baseline (speedup 1.0000x reference)
#include <cuda_runtime.h>
#include <math.h>

#define NB 4
#define NL 2048
#define ND 1024
#define NH 16
#define DH 64
#define ND3 (3*ND)
#define SSTR 68

// Scratch (allocation-free: __device__ globals)
__device__ float g_qkv[(size_t)NB*NL*ND3];      // 100.7 MB
__device__ float g_q[(size_t)NB*NH*NL*DH];      // 33.5 MB (roped Q, [b,h,l,d])
__device__ float g_k[(size_t)NB*NH*NL*DH];      // 33.5 MB (roped K, [b,h,l,d])
__device__ float g_attn[(size_t)NB*NL*ND];      // 33.5 MB (attn out, [b,l,d])

// ---------------------------------------------------------------------------
// Classic tiled SGEMM with fused bias: C[M,N] = A[M,K] @ B[K,N] + bias[N]
// BM=BN=128, BK=8, 256 threads, 8x8 micro-tile.
// ---------------------------------------------------------------------------
__global__ __launch_bounds__(256) void sgemm_bias(
    const float* __restrict__ A, const float* __restrict__ Bm,
    const float* __restrict__ bias, float* __restrict__ C,
    int M, int N, int K)
{
    constexpr int BM = 128, BN = 128, BK = 8, TM = 8, TN = 8;
    __shared__ float As[BK][BM];
    __shared__ float Bs[BK][BN];
    const int tid = threadIdx.x;
    const float* A0 = A + (size_t)blockIdx.y * BM * K;
    const float* B0 = Bm + (size_t)blockIdx.x * BN;

    float acc[TM][TN];
#pragma unroll
    for (int i = 0; i < TM; i++)
#pragma unroll
        for (int j = 0; j < TN; j++) acc[i][j] = 0.f;

    const int arow = tid >> 1, acol = (tid & 1) << 2;   // A tile 128x8
    const int brow = tid >> 5, bcol = (tid & 31) << 2;  // B tile 8x128
    const int trow = (tid >> 4) * TM, tcol = (tid & 15) * TN;

    for (int k0 = 0; k0 < K; k0 += BK) {
        float4 av = *(const float4*)(A0 + (size_t)arow * K + k0 + acol);
        float4 bv = *(const float4*)(B0 + (size_t)(k0 + brow) * N + bcol);
        __syncthreads();
        As[acol + 0][arow] = av.x; As[acol + 1][arow] = av.y;
        As[acol + 2][arow] = av.z; As[acol + 3][arow] = av.w;
        *(float4*)&Bs[brow][bcol] = bv;
        __syncthreads();
#pragma unroll
        for (int kk = 0; kk < BK; kk++) {
            float af[TM], bf[TN];
            *(float4*)&af[0] = *(const float4*)&As[kk][trow];
            *(float4*)&af[4] = *(const float4*)&As[kk][trow + 4];
            *(float4*)&bf[0] = *(const float4*)&Bs[kk][tcol];
            *(float4*)&bf[4] = *(const float4*)&Bs[kk][tcol + 4];
#pragma unroll
            for (int i = 0; i < TM; i++)
#pragma unroll
                for (int j = 0; j < TN; j++)
                    acc[i][j] = fmaf(af[i], bf[j], acc[i][j]);
        }
    }

    const int rbase = blockIdx.y * BM + trow;
    const int cbase = blockIdx.x * BN + tcol;
#pragma unroll
    for (int i = 0; i < TM; i++) {
#pragma unroll
        for (int j = 0; j < TN; j += 4) {
            float4 o;
            o.x = acc[i][j + 0] + bias[cbase + j + 0];
            o.y = acc[i][j + 1] + bias[cbase + j + 1];
            o.z = acc[i][j + 2] + bias[cbase + j + 2];
            o.w = acc[i][j + 3] + bias[cbase + j + 3];
            *(float4*)(C + (size_t)(rbase + i) * N + cbase + j) = o;
        }
    }
}

// ---------------------------------------------------------------------------
// RoPE: read q,k halves from qkv buffer, write roped Q,K in [b,h,l,d] layout.
// One thread per (b,l,h,pair).
// ---------------------------------------------------------------------------
__global__ void rope_kernel(const float* __restrict__ qkv,
                            float* __restrict__ Qo, float* __restrict__ Ko)
{
    int idx = blockIdx.x * blockDim.x + threadIdx.x;
    const int total = NB * NL * NH * (DH / 2);
    if (idx >= total) return;
    int i = idx & 31;            // pair index 0..31
    int h = (idx >> 5) & 15;
    int l = (idx >> 9) & (NL - 1);
    int b = idx >> 20;           // 32*16*2048 = 2^20

    float inv = powf(10000.0f, -(float)(2 * i) / (float)DH);
    float ang = (float)l * inv;
    float sn, cs;
    sincosf(ang, &sn, &cs);

    const float* base = qkv + (size_t)(b * NL + l) * ND3 + h * DH + 2 * i;
    float2 q = *(const float2*)(base);
    float2 k = *(const float2*)(base + ND);
    size_t o = ((size_t)(b * NH + h) * NL + l) * DH + 2 * i;
    *(float2*)(Qo + o) = make_float2(q.x * cs - q.y * sn, q.x * sn + q.y * cs);
    *(float2*)(Ko + o) = make_float2(k.x * cs - k.y * sn, k.x * sn + k.y * cs);
}

// ---------------------------------------------------------------------------
// Flash attention, fp32 SIMT. Grid: (L/64 query tiles, B*H). 256 threads.
// Online softmax with running (m, l). V read directly from qkv buffer.
// Output written in [b, l, h*DH+d] layout (ready for proj GEMM).
// ---------------------------------------------------------------------------
__global__ __launch_bounds__(256) void attn_kernel(
    const float* __restrict__ Qg, const float* __restrict__ Kg,
    const float* __restrict__ qkv, const int* __restrict__ amask,
    float* __restrict__ out)
{
    extern __shared__ float sm[];
    float* Qs  = sm;               // [d][SSTR]  (transposed)
    float* Ks  = Qs + 64 * SSTR;   // [d][SSTR]  (transposed)
    float* Vs  = Ks + 64 * SSTR;   // [key][SSTR]
    float* Ss  = Vs + 64 * SSTR;   // [row][SSTR]  S then P in-place
    float* m_s = Ss + 64 * SSTR;   // [64]
    float* l_s = m_s + 64;         // [64]
    float* al_s = l_s + 64;        // [64]
    float* red = al_s + 64;        // [64][4]
    float* msk = red + 256;        // [64]

    const int tid = threadIdx.x;
    const int qt = blockIdx.x;
    const int bh = blockIdx.y;
    const int b = bh >> 4, h = bh & 15;
    const int q0 = qt * 64;

    const float* Qp = Qg + ((size_t)bh * NL + q0) * DH;
    const float* Kp = Kg + (size_t)bh * NL * DH;
    const float* Vp = qkv + (size_t)b * NL * ND3 + 2 * ND + h * DH;

    // Load Q tile transposed into smem
    for (int t = tid; t < 64 * 16; t += 256) {
        int r = t >> 4, d4 = (t & 15) << 2;
        float4 v = *(const float4*)(Qp + r * DH + d4);
        Qs[(d4 + 0) * SSTR + r] = v.x;
        Qs[(d4 + 1) * SSTR + r] = v.y;
        Qs[(d4 + 2) * SSTR + r] = v.z;
        Qs[(d4 + 3) * SSTR + r] = v.w;
    }
    if (tid < 64) { m_s[tid] = -1e30f; l_s[tid] = 0.f; }

    const int ty = tid >> 4, tx = tid & 15;
    const int r0 = ty << 2, c0 = tx << 2;
    const int rr = tid >> 2, seg = tid & 3;

    float o[4][4];
#pragma unroll
    for (int i = 0; i < 4; i++)
#pragma unroll
        for (int j = 0; j < 4; j++) o[i][j] = 0.f;

    for (int kt = 0; kt <= qt; kt++) {
        __syncthreads();  // previous iteration fully consumed Ks/Vs/Ss
        // Load K tile (transposed) + V tile
        for (int t = tid; t < 64 * 16; t += 256) {
            int key = t >> 4, d4 = (t & 15) << 2;
            float4 kv = *(const float4*)(Kp + (size_t)(kt * 64 + key) * DH + d4);
            Ks[(d4 + 0) * SSTR + key] = kv.x;
            Ks[(d4 + 1) * SSTR + key] = kv.y;
            Ks[(d4 + 2) * SSTR + key] = kv.z;
            Ks[(d4 + 3) * SSTR + key] = kv.w;
            float4 vv = *(const float4*)(Vp + (size_t)(kt * 64 + key) * ND3 + d4);
            *(float4*)&Vs[key * SSTR + d4] = vv;
        }
        if (tid < 64)
            msk[tid] = amask[b * NL + kt * 64 + tid] ? 0.f : -1e30f;
        __syncthreads();

        // S = Q K^T (4x4 micro-tile per thread)
        float s[4][4];
#pragma unroll
        for (int i = 0; i < 4; i++)
#pragma unroll
            for (int j = 0; j < 4; j++) s[i][j] = 0.f;
#pragma unroll 4
        for (int d = 0; d < 64; d++) {
            float4 qf = *(const float4*)&Qs[d * SSTR + r0];
            float4 kf = *(const float4*)&Ks[d * SSTR + c0];
            float qa[4] = {qf.x, qf.y, qf.z, qf.w};
            float ka[4] = {kf.x, kf.y, kf.z, kf.w};
#pragma unroll
            for (int i = 0; i < 4; i++)
#pragma unroll
                for (int j = 0; j < 4; j++)
                    s[i][j] = fmaf(qa[i], ka[j], s[i][j]);
        }
        const float scl = 0.125f;  // 1/sqrt(64)
#pragma unroll
        for (int i = 0; i < 4; i++) {
#pragma unroll
            for (int j = 0; j < 4; j++) {
                float v = s[i][j] * scl + msk[c0 + j];
                if (kt == qt && (c0 + j) > (r0 + i)) v = -1e30f;
                Ss[(r0 + i) * SSTR + c0 + j] = v;
            }
        }
        __syncthreads();

        // Row max (partial, 4 threads per row)
        {
            float lm = -1e30f;
            const float* row = &Ss[rr * SSTR + seg * 16];
#pragma unroll
            for (int j = 0; j < 16; j++) lm = fmaxf(lm, row[j]);
            red[rr * 4 + seg] = lm;
        }
        __syncthreads();
        if (tid < 64) {
            float tm = fmaxf(fmaxf(red[tid*4], red[tid*4+1]),
                             fmaxf(red[tid*4+2], red[tid*4+3]));
            float nm = fmaxf(m_s[tid], tm);
            al_s[tid] = __expf(m_s[tid] - nm);
            m_s[tid] = nm;
        }
        __syncthreads();

        // exp in place + partial sums
        {
            float nm = m_s[rr];
            float* row = &Ss[rr * SSTR + seg * 16];
            float ps = 0.f;
#pragma unroll
            for (int j = 0; j < 16; j++) {
                float e = __expf(row[j] - nm);
                row[j] = e;
                ps += e;
            }
            red[rr * 4 + seg] = ps;
        }
        __syncthreads();
        if (tid < 64)
            l_s[tid] = l_s[tid] * al_s[tid] +
                       (red[tid*4] + red[tid*4+1] + red[tid*4+2] + red[tid*4+3]);
        __syncthreads();

        // O = O*alpha + P V
        float a0 = al_s[r0], a1 = al_s[r0+1], a2 = al_s[r0+2], a3 = al_s[r0+3];
#pragma unroll
        for (int j = 0; j < 4; j++) {
            o[0][j] *= a0; o[1][j] *= a1; o[2][j] *= a2; o[3][j] *= a3;
        }
#pragma unroll 4
        for (int c = 0; c < 64; c++) {
            float4 vf = *(const float4*)&Vs[c * SSTR + c0];
            float p0 = Ss[(r0+0) * SSTR + c];
            float p1 = Ss[(r0+1) * SSTR + c];
            float p2 = Ss[(r0+2) * SSTR + c];
            float p3 = Ss[(r0+3) * SSTR + c];
            o[0][0] = fmaf(p0, vf.x, o[0][0]); o[0][1] = fmaf(p0, vf.y, o[0][1]);
            o[0][2] = fmaf(p0, vf.z, o[0][2]); o[0][3] = fmaf(p0, vf.w, o[0][3]);
            o[1][0] = fmaf(p1, vf.x, o[1][0]); o[1][1] = fmaf(p1, vf.y, o[1][1]);
            o[1][2] = fmaf(p1, vf.z, o[1][2]); o[1][3] = fmaf(p1, vf.w, o[1][3]);
            o[2][0] = fmaf(p2, vf.x, o[2][0]); o[2][1] = fmaf(p2, vf.y, o[2][1]);
            o[2][2] = fmaf(p2, vf.z, o[2][2]); o[2][3] = fmaf(p2, vf.w, o[2][3]);
            o[3][0] = fmaf(p3, vf.x, o[3][0]); o[3][1] = fmaf(p3, vf.y, o[3][1]);
            o[3][2] = fmaf(p3, vf.z, o[3][2]); o[3][3] = fmaf(p3, vf.w, o[3][3]);
        }
    }

    // Finalize: divide by l, write [b, l, h*DH + d]
    float* op = out + (size_t)(b * NL + q0) * ND + h * DH;
#pragma unroll
    for (int i = 0; i < 4; i++) {
        float inv = 1.f / l_s[r0 + i];
        float4 w = make_float4(o[i][0] * inv, o[i][1] * inv,
                               o[i][2] * inv, o[i][3] * inv);
        *(float4*)(op + (size_t)(r0 + i) * ND + c0) = w;
    }
}

// ---------------------------------------------------------------------------
extern "C" void kernel_launch(void* const* d_in, const int* in_sizes, int n_in,
                              void* d_out, int out_size)
{
    const float* x     = (const float*)d_in[0];
    const float* Wqkv  = (const float*)d_in[1];
    const float* bqkv  = (const float*)d_in[2];
    const float* Wproj = (const float*)d_in[3];
    const float* bproj = (const float*)d_in[4];
    const int*   amask = (const int*)d_in[5];
    float* out = (float*)d_out;

    float *qkv, *q, *k, *attn;
    cudaGetSymbolAddress((void**)&qkv,  g_qkv);
    cudaGetSymbolAddress((void**)&q,    g_q);
    cudaGetSymbolAddress((void**)&k,    g_k);
    cudaGetSymbolAddress((void**)&attn, g_attn);

    // 1) QKV projection: [8192,1024] @ [1024,3072] + b
    sgemm_bias<<<dim3(ND3 / 128, (NB * NL) / 128), 256>>>(
        x, Wqkv, bqkv, qkv, NB * NL, ND3, ND);

    // 2) RoPE -> Q,K in [b,h,l,d]
    int total = NB * NL * NH * (DH / 2);
    rope_kernel<<<(total + 255) / 256, 256>>>(qkv, q, k);

    // 3) Attention
    int smem = (4 * 64 * SSTR + 64 * 3 + 256 + 64) * (int)sizeof(float);
    cudaFuncSetAttribute(attn_kernel,
                         cudaFuncAttributeMaxDynamicSharedMemorySize, smem);
    attn_kernel<<<dim3(NL / 64, NB * NH), 256, smem>>>(q, k, qkv, amask, attn);

    // 4) Output projection: [8192,1024] @ [1024,1024] + b
    sgemm_bias<<<dim3(ND / 128, (NB * NL) / 128), 256>>>(
        attn, Wproj, bproj, out, NB * NL, ND, ND);
}

// round 3
// speedup vs baseline: 2.5308x; 2.5308x over previous
#include <cuda_runtime.h>
#include <math.h>

#define NB 4
#define NL 2048
#define ND 1024
#define NH 16
#define DH 64
#define ND3 (3*ND)

// Scratch (allocation-free: __device__ globals)
__device__ float g_qkv[(size_t)NB*NL*ND3];      // 100.7 MB
__device__ float g_q[(size_t)NB*NH*NL*DH];      // 33.5 MB (roped Q, [b,h,l,d])
__device__ float g_k[(size_t)NB*NH*NL*DH];      // 33.5 MB (roped K, [b,h,l,d])
__device__ float g_attn[(size_t)NB*NL*ND];      // 33.5 MB (attn out, [b,l,d])

__device__ __forceinline__ unsigned f2tf(float f) {
    unsigned u;
    asm("cvt.rna.tf32.f32 %0, %1;" : "=r"(u) : "f"(f));
    return u;
}

__device__ __forceinline__ void mma8(float* d, const unsigned* a,
                                     unsigned b0, unsigned b1) {
    asm volatile(
        "mma.sync.aligned.m16n8k8.row.col.f32.tf32.tf32.f32 "
        "{%0,%1,%2,%3}, {%4,%5,%6,%7}, {%8,%9}, {%0,%1,%2,%3};"
        : "+f"(d[0]), "+f"(d[1]), "+f"(d[2]), "+f"(d[3])
        : "r"(a[0]), "r"(a[1]), "r"(a[2]), "r"(a[3]), "r"(b0), "r"(b1));
}

// ---------------------------------------------------------------------------
// TF32 tensor-core GEMM with fused bias: C[M,N] = A[M,K] @ B[K,N] + bias[N]
// CTA tile 128x128, BK=32. 8 warps, warp tile 32x64 (4m x 2n grid of warps).
// ---------------------------------------------------------------------------
__global__ __launch_bounds__(256) void gemm_tf32(
    const float* __restrict__ A, const float* __restrict__ B,
    const float* __restrict__ bias, float* __restrict__ C,
    int M, int N, int K)
{
    __shared__ unsigned As[32 * 136];   // [k][m], stride 136 (bank 8t+g: CF)
    __shared__ unsigned Bs[32 * 136];   // [k][n]

    const int tid = threadIdx.x;
    const int lane = tid & 31, wid = tid >> 5;
    const int wm = wid >> 1, wn = wid & 1;
    const int g = lane >> 2, t = lane & 3;

    const float* Ab = A + (size_t)blockIdx.y * 128 * K;
    const float* Bb = B + (size_t)blockIdx.x * 128;

    float acc[2][8][4];
#pragma unroll
    for (int mf = 0; mf < 2; mf++)
#pragma unroll
        for (int nf = 0; nf < 8; nf++)
#pragma unroll
            for (int i = 0; i < 4; i++) acc[mf][nf][i] = 0.f;

    const int arow = tid >> 3, acol = (tid & 7) << 2;   // A: 128 x 32
    const int bkr  = tid >> 5, bcol = (tid & 31) << 2;  // B: 32 x 128

    float4 ar[4], br[4];
#pragma unroll
    for (int p = 0; p < 4; p++)
        ar[p] = *(const float4*)(Ab + (size_t)(arow + p * 32) * K + acol);
#pragma unroll
    for (int p = 0; p < 4; p++)
        br[p] = *(const float4*)(Bb + (size_t)(bkr + p * 8) * N + bcol);

    const int nt = K / 32;
    for (int tile = 0; tile < nt; tile++) {
        // store current tile (fp32 -> tf32 at STS)
#pragma unroll
        for (int p = 0; p < 4; p++) {
            int r = arow + p * 32;
            As[(acol + 0) * 136 + r] = f2tf(ar[p].x);
            As[(acol + 1) * 136 + r] = f2tf(ar[p].y);
            As[(acol + 2) * 136 + r] = f2tf(ar[p].z);
            As[(acol + 3) * 136 + r] = f2tf(ar[p].w);
            int kr = bkr + p * 8;
            uint4 w = make_uint4(f2tf(br[p].x), f2tf(br[p].y),
                                 f2tf(br[p].z), f2tf(br[p].w));
            *(uint4*)&Bs[kr * 136 + bcol] = w;
        }
        __syncthreads();

        // prefetch next tile into registers
        if (tile + 1 < nt) {
            const float* An = Ab + (tile + 1) * 32;
            const float* Bn = Bb + (size_t)(tile + 1) * 32 * N;
#pragma unroll
            for (int p = 0; p < 4; p++)
                ar[p] = *(const float4*)(An + (size_t)(arow + p * 32) * K + acol);
#pragma unroll
            for (int p = 0; p < 4; p++)
                br[p] = *(const float4*)(Bn + (size_t)(bkr + p * 8) * N + bcol);
        }

        // compute: 4 k-steps of 8
#pragma unroll
        for (int kc = 0; kc < 4; kc++) {
            const int k0 = kc * 8;
            unsigned a[2][4];
#pragma unroll
            for (int mf = 0; mf < 2; mf++) {
                int r = wm * 32 + mf * 16 + g;
                a[mf][0] = As[(k0 + t) * 136 + r];
                a[mf][1] = As[(k0 + t) * 136 + r + 8];
                a[mf][2] = As[(k0 + t + 4) * 136 + r];
                a[mf][3] = As[(k0 + t + 4) * 136 + r + 8];
            }
#pragma unroll
            for (int nf = 0; nf < 8; nf++) {
                int c = wn * 64 + nf * 8 + g;
                unsigned b0 = Bs[(k0 + t) * 136 + c];
                unsigned b1 = Bs[(k0 + t + 4) * 136 + c];
                mma8(acc[0][nf], a[0], b0, b1);
                mma8(acc[1][nf], a[1], b0, b1);
            }
        }
        __syncthreads();
    }

    // epilogue: bias + store
#pragma unroll
    for (int mf = 0; mf < 2; mf++) {
        int row = blockIdx.y * 128 + wm * 32 + mf * 16 + g;
#pragma unroll
        for (int nf = 0; nf < 8; nf++) {
            int col = blockIdx.x * 128 + wn * 64 + nf * 8 + 2 * t;
            float b0 = bias[col], b1 = bias[col + 1];
            *(float2*)(C + (size_t)row * N + col) =
                make_float2(acc[mf][nf][0] + b0, acc[mf][nf][1] + b1);
            *(float2*)(C + (size_t)(row + 8) * N + col) =
                make_float2(acc[mf][nf][2] + b0, acc[mf][nf][3] + b1);
        }
    }
}

// ---------------------------------------------------------------------------
// RoPE (unchanged): qkv -> roped Q,K in [b,h,l,d]
// ---------------------------------------------------------------------------
__global__ void rope_kernel(const float* __restrict__ qkv,
                            float* __restrict__ Qo, float* __restrict__ Ko)
{
    int idx = blockIdx.x * blockDim.x + threadIdx.x;
    const int total = NB * NL * NH * (DH / 2);
    if (idx >= total) return;
    int i = idx & 31;
    int h = (idx >> 5) & 15;
    int l = (idx >> 9) & (NL - 1);
    int b = idx >> 20;

    float inv = powf(10000.0f, -(float)(2 * i) / (float)DH);
    float ang = (float)l * inv;
    float sn, cs;
    sincosf(ang, &sn, &cs);

    const float* base = qkv + (size_t)(b * NL + l) * ND3 + h * DH + 2 * i;
    float2 q = *(const float2*)(base);
    float2 k = *(const float2*)(base + ND);
    size_t o = ((size_t)(b * NH + h) * NL + l) * DH + 2 * i;
    *(float2*)(Qo + o) = make_float2(q.x * cs - q.y * sn, q.x * sn + q.y * cs);
    *(float2*)(Ko + o) = make_float2(k.x * cs - k.y * sn, k.x * sn + k.y * cs);
}

// ---------------------------------------------------------------------------
// TF32 tensor-core flash attention.
// q-tile = 256 (8 warps x 32 rows), key-tile = 64, double-buffered K/V.
// Grid: (NL/256, B*H). 256 threads. Heavy q-tiles launched first.
// ---------------------------------------------------------------------------
#define QT 256
#define KT 64
#define QSTR 68
#define VSTR 72

__global__ __launch_bounds__(256, 1) void attn_tf32(
    const float* __restrict__ Qg, const float* __restrict__ Kg,
    const float* __restrict__ qkv, const int* __restrict__ amask,
    float* __restrict__ out)
{
    extern __shared__ unsigned smem_u[];
    unsigned* Qs = smem_u;                        // [256][68]
    unsigned* Ks = Qs + QT * QSTR;                // 2 x [64][68]
    unsigned* Vs = Ks + 2 * KT * QSTR;            // 2 x [64][72]
    unsigned* Ps = Vs + 2 * KT * VSTR;            // 8 warps x [32][68]
    float* msk  = (float*)(Ps + 8 * 32 * QSTR);   // 2 x [64]

    const int tid = threadIdx.x;
    const int lane = tid & 31, wid = tid >> 5;
    const int g = lane >> 2, t = lane & 3;
    const int qt = (gridDim.x - 1) - blockIdx.x;  // heavy tiles first
    const int bh = blockIdx.y;
    const int b = bh >> 4, h = bh & 15;
    const int q0 = qt * QT;
    const int ktmax = 4 * qt + 3;

    const float* Qp = Qg + ((size_t)bh * NL + q0) * DH;
    const float* Kp = Kg + (size_t)bh * NL * DH;
    const float* Vp = qkv + (size_t)b * NL * ND3 + 2 * ND + h * DH;

    // load Q tile (fp32 -> tf32)
    for (int i = tid; i < QT * 16; i += 256) {
        int r = i >> 4, c4 = (i & 15) << 2;
        float4 v = *(const float4*)(Qp + (size_t)r * DH + c4);
        uint4 w = make_uint4(f2tf(v.x), f2tf(v.y), f2tf(v.z), f2tf(v.w));
        *(uint4*)&Qs[r * QSTR + c4] = w;
    }

    // K/V tile 0 into registers
    const int krow = tid >> 4, kc4 = (tid & 15) << 2;
    float4 kr[4], vr[4];
    float mreg;
#pragma unroll
    for (int p = 0; p < 4; p++) {
        kr[p] = *(const float4*)(Kp + (size_t)(krow + p * 16) * DH + kc4);
        vr[p] = *(const float4*)(Vp + (size_t)(krow + p * 16) * ND3 + kc4);
    }
    mreg = (tid < KT) ? (amask[b * NL + tid] ? 0.f : -1e30f) : 0.f;

    __syncthreads();
    // store tile 0 into buf 0
#pragma unroll
    for (int p = 0; p < 4; p++) {
        int r = krow + p * 16;
        *(uint4*)&Ks[r * QSTR + kc4] = make_uint4(f2tf(kr[p].x), f2tf(kr[p].y),
                                                  f2tf(kr[p].z), f2tf(kr[p].w));
        *(uint4*)&Vs[r * VSTR + kc4] = make_uint4(f2tf(vr[p].x), f2tf(vr[p].y),
                                                  f2tf(vr[p].z), f2tf(vr[p].w));
    }
    if (tid < KT) msk[tid] = mreg;
    __syncthreads();

    float o[2][8][4];
#pragma unroll
    for (int mf = 0; mf < 2; mf++)
#pragma unroll
        for (int nf = 0; nf < 8; nf++)
#pragma unroll
            for (int i = 0; i < 4; i++) o[mf][nf][i] = 0.f;
    float m_st[2][2], l_st[2][2];
#pragma unroll
    for (int mf = 0; mf < 2; mf++) {
        m_st[mf][0] = m_st[mf][1] = -1e30f;
        l_st[mf][0] = l_st[mf][1] = 0.f;
    }

    const int wq = wid * 32;
    const int pbase = wid * 32 * QSTR;

    for (int kt = 0; kt <= ktmax; kt++) {
        const int buf = kt & 1;
        const unsigned* Kb = Ks + buf * KT * QSTR;
        const unsigned* Vb = Vs + buf * KT * VSTR;
        const float* mb = msk + buf * KT;
        const bool have_next = (kt < ktmax);

        // prefetch next K/V tile
        if (have_next) {
#pragma unroll
            for (int p = 0; p < 4; p++) {
                size_t rg = (size_t)((kt + 1) * KT + krow + p * 16);
                kr[p] = *(const float4*)(Kp + rg * DH + kc4);
                vr[p] = *(const float4*)(Vp + rg * ND3 + kc4);
            }
            mreg = (tid < KT) ?
                (amask[b * NL + (kt + 1) * KT + tid] ? 0.f : -1e30f) : 0.f;
        }

        // ---- S = Q K^T ----
        float s[2][8][4];
#pragma unroll
        for (int mf = 0; mf < 2; mf++)
#pragma unroll
            for (int nf = 0; nf < 8; nf++)
#pragma unroll
                for (int i = 0; i < 4; i++) s[mf][nf][i] = 0.f;

#pragma unroll
        for (int kc = 0; kc < 8; kc++) {
            const int k0 = kc * 8;
            unsigned a[2][4];
#pragma unroll
            for (int mf = 0; mf < 2; mf++) {
                int r = wq + mf * 16 + g;
                a[mf][0] = Qs[r * QSTR + k0 + t];
                a[mf][1] = Qs[(r + 8) * QSTR + k0 + t];
                a[mf][2] = Qs[r * QSTR + k0 + t + 4];
                a[mf][3] = Qs[(r + 8) * QSTR + k0 + t + 4];
            }
#pragma unroll
            for (int nf = 0; nf < 8; nf++) {
                unsigned b0 = Kb[(nf * 8 + g) * QSTR + k0 + t];
                unsigned b1 = Kb[(nf * 8 + g) * QSTR + k0 + t + 4];
                mma8(s[0][nf], a[0], b0, b1);
                mma8(s[1][nf], a[1], b0, b1);
            }
        }

        const bool diag = (kt * KT + KT - 1 > q0);  // causal masking needed

        // ---- softmax + P store ----
#pragma unroll
        for (int mf = 0; mf < 2; mf++) {
            const int rlo = q0 + wq + mf * 16 + g;
            const int rhi = rlo + 8;
#pragma unroll
            for (int nf = 0; nf < 8; nf++) {
                int c = kt * KT + nf * 8 + 2 * t;
                float mk0 = mb[nf * 8 + 2 * t];
                float mk1 = mb[nf * 8 + 2 * t + 1];
                float* sv = s[mf][nf];
                sv[0] = sv[0] * 0.125f + mk0;
                sv[1] = sv[1] * 0.125f + mk1;
                sv[2] = sv[2] * 0.125f + mk0;
                sv[3] = sv[3] * 0.125f + mk1;
                if (diag) {
                    if (c     > rlo) sv[0] = -1e30f;
                    if (c + 1 > rlo) sv[1] = -1e30f;
                    if (c     > rhi) sv[2] = -1e30f;
                    if (c + 1 > rhi) sv[3] = -1e30f;
                }
            }
            float mx0 = -1e30f, mx1 = -1e30f;
#pragma unroll
            for (int nf = 0; nf < 8; nf++) {
                mx0 = fmaxf(mx0, fmaxf(s[mf][nf][0], s[mf][nf][1]));
                mx1 = fmaxf(mx1, fmaxf(s[mf][nf][2], s[mf][nf][3]));
            }
            mx0 = fmaxf(mx0, __shfl_xor_sync(0xffffffffu, mx0, 1));
            mx0 = fmaxf(mx0, __shfl_xor_sync(0xffffffffu, mx0, 2));
            mx1 = fmaxf(mx1, __shfl_xor_sync(0xffffffffu, mx1, 1));
            mx1 = fmaxf(mx1, __shfl_xor_sync(0xffffffffu, mx1, 2));

            float nm0 = fmaxf(m_st[mf][0], mx0);
            float nm1 = fmaxf(m_st[mf][1], mx1);
            float al0 = __expf(m_st[mf][0] - nm0);
            float al1 = __expf(m_st[mf][1] - nm1);
            m_st[mf][0] = nm0; m_st[mf][1] = nm1;

            float sum0 = 0.f, sum1 = 0.f;
#pragma unroll
            for (int nf = 0; nf < 8; nf++) {
                float* sv = s[mf][nf];
                sv[0] = __expf(sv[0] - nm0); sum0 += sv[0];
                sv[1] = __expf(sv[1] - nm0); sum0 += sv[1];
                sv[2] = __expf(sv[2] - nm1); sum1 += sv[2];
                sv[3] = __expf(sv[3] - nm1); sum1 += sv[3];
            }
            sum0 += __shfl_xor_sync(0xffffffffu, sum0, 1);
            sum0 += __shfl_xor_sync(0xffffffffu, sum0, 2);
            sum1 += __shfl_xor_sync(0xffffffffu, sum1, 1);
            sum1 += __shfl_xor_sync(0xffffffffu, sum1, 2);
            l_st[mf][0] = l_st[mf][0] * al0 + sum0;
            l_st[mf][1] = l_st[mf][1] * al1 + sum1;

#pragma unroll
            for (int nf = 0; nf < 8; nf++) {
                o[mf][nf][0] *= al0; o[mf][nf][1] *= al0;
                o[mf][nf][2] *= al1; o[mf][nf][3] *= al1;
            }

            // store P (tf32) into per-warp private region
            int pr = pbase + (mf * 16 + g) * QSTR;
#pragma unroll
            for (int nf = 0; nf < 8; nf++) {
                int col = nf * 8 + 2 * t;
                *(uint2*)&Ps[pr + col] =
                    make_uint2(f2tf(s[mf][nf][0]), f2tf(s[mf][nf][1]));
                *(uint2*)&Ps[pr + 8 * QSTR + col] =
                    make_uint2(f2tf(s[mf][nf][2]), f2tf(s[mf][nf][3]));
            }
        }
        __syncwarp();

        // ---- O += P V ----
#pragma unroll
        for (int kc = 0; kc < 8; kc++) {
            const int k0 = kc * 8;
            unsigned a[2][4];
#pragma unroll
            for (int mf = 0; mf < 2; mf++) {
                int r = mf * 16 + g;
                a[mf][0] = Ps[pbase + r * QSTR + k0 + t];
                a[mf][1] = Ps[pbase + (r + 8) * QSTR + k0 + t];
                a[mf][2] = Ps[pbase + r * QSTR + k0 + t + 4];
                a[mf][3] = Ps[pbase + (r + 8) * QSTR + k0 + t + 4];
            }
#pragma unroll
            for (int nf = 0; nf < 8; nf++) {
                unsigned b0 = Vb[(k0 + t) * VSTR + nf * 8 + g];
                unsigned b1 = Vb[(k0 + t + 4) * VSTR + nf * 8 + g];
                mma8(o[0][nf], a[0], b0, b1);
                mma8(o[1][nf], a[1], b0, b1);
            }
        }

        // commit next tile to other buffer
        if (have_next) {
            __syncthreads();
            unsigned* Kn = Ks + (buf ^ 1) * KT * QSTR;
            unsigned* Vn = Vs + (buf ^ 1) * KT * VSTR;
#pragma unroll
            for (int p = 0; p < 4; p++) {
                int r = krow + p * 16;
                *(uint4*)&Kn[r * QSTR + kc4] =
                    make_uint4(f2tf(kr[p].x), f2tf(kr[p].y),
                               f2tf(kr[p].z), f2tf(kr[p].w));
                *(uint4*)&Vn[r * VSTR + kc4] =
                    make_uint4(f2tf(vr[p].x), f2tf(vr[p].y),
                               f2tf(vr[p].z), f2tf(vr[p].w));
            }
            if (tid < KT) msk[(buf ^ 1) * KT + tid] = mreg;
            __syncthreads();
        }
    }

    // ---- finalize: O / l, write [b, l, h*64 + d] ----
#pragma unroll
    for (int mf = 0; mf < 2; mf++) {
        float inv0 = 1.f / l_st[mf][0];
        float inv1 = 1.f / l_st[mf][1];
        int rlo = q0 + wq + mf * 16 + g;
        float* op = out + ((size_t)b * NL + rlo) * ND + h * DH;
#pragma unroll
        for (int nf = 0; nf < 8; nf++) {
            int col = nf * 8 + 2 * t;
            *(float2*)(op + col) =
                make_float2(o[mf][nf][0] * inv0, o[mf][nf][1] * inv0);
            *(float2*)(op + (size_t)8 * ND + col) =
                make_float2(o[mf][nf][2] * inv1, o[mf][nf][3] * inv1);
        }
    }
}

// ---------------------------------------------------------------------------
extern "C" void kernel_launch(void* const* d_in, const int* in_sizes, int n_in,
                              void* d_out, int out_size)
{
    const float* x     = (const float*)d_in[0];
    const float* Wqkv  = (const float*)d_in[1];
    const float* bqkv  = (const float*)d_in[2];
    const float* Wproj = (const float*)d_in[3];
    const float* bproj = (const float*)d_in[4];
    const int*   amask = (const int*)d_in[5];
    float* out = (float*)d_out;

    float *qkv, *q, *k, *attn;
    cudaGetSymbolAddress((void**)&qkv,  g_qkv);
    cudaGetSymbolAddress((void**)&q,    g_q);
    cudaGetSymbolAddress((void**)&k,    g_k);
    cudaGetSymbolAddress((void**)&attn, g_attn);

    // 1) QKV projection: [8192,1024] @ [1024,3072] + b
    gemm_tf32<<<dim3(ND3 / 128, (NB * NL) / 128), 256>>>(
        x, Wqkv, bqkv, qkv, NB * NL, ND3, ND);

    // 2) RoPE -> Q,K in [b,h,l,d]
    int total = NB * NL * NH * (DH / 2);
    rope_kernel<<<(total + 255) / 256, 256>>>(qkv, q, k);

    // 3) Attention (tf32 tensor cores)
    size_t smem = (size_t)(QT * QSTR + 2 * KT * QSTR + 2 * KT * VSTR +
                           8 * 32 * QSTR) * 4 + 2 * KT * 4;
    cudaFuncSetAttribute(attn_tf32,
                         cudaFuncAttributeMaxDynamicSharedMemorySize,
                         (int)smem);
    attn_tf32<<<dim3(NL / QT, NB * NH), 256, smem>>>(q, k, qkv, amask, attn);

    // 4) Output projection: [8192,1024] @ [1024,1024] + b
    gemm_tf32<<<dim3(ND / 128, (NB * NL) / 128), 256>>>(
        attn, Wproj, bproj, out, NB * NL, ND, ND);
}

// round 4
// speedup vs baseline: 3.1995x; 1.2642x over previous
#include <cuda_runtime.h>
#include <math.h>

#define NB 4
#define NL 2048
#define ND 1024
#define NH 16
#define DH 64
#define ND3 (3*ND)

// Scratch (allocation-free: __device__ globals)
__device__ float g_qkv[(size_t)NB*NL*ND3];
__device__ float g_q[(size_t)NB*NH*NL*DH];
__device__ float g_k[(size_t)NB*NH*NL*DH];
__device__ float g_attn[(size_t)NB*NL*ND];

__device__ __forceinline__ unsigned f2tf(float f) {
    unsigned u;
    asm("cvt.rna.tf32.f32 %0, %1;" : "=r"(u) : "f"(f));
    return u;
}

__device__ __forceinline__ void mma8(float* d, const unsigned* a,
                                     unsigned b0, unsigned b1) {
    asm volatile(
        "mma.sync.aligned.m16n8k8.row.col.f32.tf32.tf32.f32 "
        "{%0,%1,%2,%3}, {%4,%5,%6,%7}, {%8,%9}, {%0,%1,%2,%3};"
        : "+f"(d[0]), "+f"(d[1]), "+f"(d[2]), "+f"(d[3])
        : "r"(a[0]), "r"(a[1]), "r"(a[2]), "r"(a[3]), "r"(b0), "r"(b1));
}

__device__ __forceinline__ void ldsm4(unsigned* r, unsigned addr) {
    asm volatile(
        "ldmatrix.sync.aligned.m8n8.x4.shared.b16 {%0,%1,%2,%3}, [%4];"
        : "=r"(r[0]), "=r"(r[1]), "=r"(r[2]), "=r"(r[3]) : "r"(addr));
}

// ---------------------------------------------------------------------------
// TF32 GEMM + bias. CTA 128x128, BK=32, 8 warps (4m x 2n), warp tile 32x64.
// A in SMEM as [m][k] (stride 36) fed via LDSM; B as [k][n] (stride 136).
// ---------------------------------------------------------------------------
__global__ __launch_bounds__(256) void gemm_tf32(
    const float* __restrict__ A, const float* __restrict__ B,
    const float* __restrict__ bias, float* __restrict__ C,
    int M, int N, int K)
{
    __shared__ unsigned As[128 * 36];   // [m][k]
    __shared__ unsigned Bs[32 * 136];   // [k][n]

    const int tid = threadIdx.x;
    const int lane = tid & 31, wid = tid >> 5;
    const int wm = wid >> 1, wn = wid & 1;
    const int g = lane >> 2, t = lane & 3;

    const float* Ab = A + (size_t)blockIdx.y * 128 * K;
    const float* Bb = B + (size_t)blockIdx.x * 128;

    float acc[2][8][4];
#pragma unroll
    for (int mf = 0; mf < 2; mf++)
#pragma unroll
        for (int nf = 0; nf < 8; nf++)
#pragma unroll
            for (int i = 0; i < 4; i++) acc[mf][nf][i] = 0.f;

    const int arow = tid >> 3, acol = (tid & 7) << 2;   // A: 128 x 32
    const int bkr  = tid >> 5, bcol = (tid & 31) << 2;  // B: 32 x 128

    // LDSM base addresses for A (per mf)
    unsigned asm_base[2];
    {
        unsigned as0 = (unsigned)__cvta_generic_to_shared(As);
#pragma unroll
        for (int mf = 0; mf < 2; mf++) {
            int row = wm * 32 + mf * 16 + (lane & 15);
            int col = (lane >> 4) << 2;
            asm_base[mf] = as0 + (row * 36 + col) * 4;
        }
    }

    float4 ar[4], br[4];
#pragma unroll
    for (int p = 0; p < 4; p++)
        ar[p] = *(const float4*)(Ab + (size_t)(arow + p * 32) * K + acol);
#pragma unroll
    for (int p = 0; p < 4; p++)
        br[p] = *(const float4*)(Bb + (size_t)(bkr + p * 8) * N + bcol);

    const int nt = K / 32;
    for (int tile = 0; tile < nt; tile++) {
#pragma unroll
        for (int p = 0; p < 4; p++) {
            int r = arow + p * 32;
            *(uint4*)&As[r * 36 + acol] =
                make_uint4(f2tf(ar[p].x), f2tf(ar[p].y),
                           f2tf(ar[p].z), f2tf(ar[p].w));
            int kr = bkr + p * 8;
            *(uint4*)&Bs[kr * 136 + bcol] =
                make_uint4(f2tf(br[p].x), f2tf(br[p].y),
                           f2tf(br[p].z), f2tf(br[p].w));
        }
        __syncthreads();

        if (tile + 1 < nt) {
            const float* An = Ab + (tile + 1) * 32;
            const float* Bn = Bb + (size_t)(tile + 1) * 32 * N;
#pragma unroll
            for (int p = 0; p < 4; p++)
                ar[p] = *(const float4*)(An + (size_t)(arow + p * 32) * K + acol);
#pragma unroll
            for (int p = 0; p < 4; p++)
                br[p] = *(const float4*)(Bn + (size_t)(bkr + p * 8) * N + bcol);
        }

#pragma unroll
        for (int kc = 0; kc < 4; kc++) {
            const int k0 = kc * 8;
            unsigned a[2][4];
            ldsm4(a[0], asm_base[0] + k0 * 4);
            ldsm4(a[1], asm_base[1] + k0 * 4);
#pragma unroll
            for (int nf = 0; nf < 8; nf++) {
                int c = wn * 64 + nf * 8 + g;
                unsigned b0 = Bs[(k0 + t) * 136 + c];
                unsigned b1 = Bs[(k0 + t + 4) * 136 + c];
                mma8(acc[0][nf], a[0], b0, b1);
                mma8(acc[1][nf], a[1], b0, b1);
            }
        }
        __syncthreads();
    }

#pragma unroll
    for (int mf = 0; mf < 2; mf++) {
        int row = blockIdx.y * 128 + wm * 32 + mf * 16 + g;
#pragma unroll
        for (int nf = 0; nf < 8; nf++) {
            int col = blockIdx.x * 128 + wn * 64 + nf * 8 + 2 * t;
            float b0 = bias[col], b1 = bias[col + 1];
            *(float2*)(C + (size_t)row * N + col) =
                make_float2(acc[mf][nf][0] + b0, acc[mf][nf][1] + b1);
            *(float2*)(C + (size_t)(row + 8) * N + col) =
                make_float2(acc[mf][nf][2] + b0, acc[mf][nf][3] + b1);
        }
    }
}

// ---------------------------------------------------------------------------
// RoPE: qkv -> roped Q,K in [b,h,l,d]
// ---------------------------------------------------------------------------
__global__ void rope_kernel(const float* __restrict__ qkv,
                            float* __restrict__ Qo, float* __restrict__ Ko)
{
    int idx = blockIdx.x * blockDim.x + threadIdx.x;
    const int total = NB * NL * NH * (DH / 2);
    if (idx >= total) return;
    int i = idx & 31;
    int h = (idx >> 5) & 15;
    int l = (idx >> 9) & (NL - 1);
    int b = idx >> 20;

    float inv = powf(10000.0f, -(float)(2 * i) / (float)DH);
    float ang = (float)l * inv;
    float sn, cs;
    sincosf(ang, &sn, &cs);

    const float* base = qkv + (size_t)(b * NL + l) * ND3 + h * DH + 2 * i;
    float2 q = *(const float2*)(base);
    float2 k = *(const float2*)(base + ND);
    size_t o = ((size_t)(b * NH + h) * NL + l) * DH + 2 * i;
    *(float2*)(Qo + o) = make_float2(q.x * cs - q.y * sn, q.x * sn + q.y * cs);
    *(float2*)(Ko + o) = make_float2(k.x * cs - k.y * sn, k.x * sn + k.y * cs);
}

// ---------------------------------------------------------------------------
// TF32 flash attention. q-tile 256 (8 warps x 32 rows), key-tile 64,
// double-buffered K/V. LDSM for Q/K, register-direct P->PV via V row
// permutation (key j within each 8-group stored at row j/2 + (j&1)*4).
// ---------------------------------------------------------------------------
#define QT 256
#define KT 64
#define QSTR 68
#define VSTR 72
#define SCL 0.1803368801111244f   /* 0.125 * log2(e) */

__global__ __launch_bounds__(256, 1) void attn_tf32(
    const float* __restrict__ Qg, const float* __restrict__ Kg,
    const float* __restrict__ qkv, const int* __restrict__ amask,
    float* __restrict__ out)
{
    extern __shared__ unsigned smem_u[];
    unsigned* Qs = smem_u;                        // [256][68]
    unsigned* Ks = Qs + QT * QSTR;                // 2 x [64][68]
    unsigned* Vs = Ks + 2 * KT * QSTR;            // 2 x [64][72] (permuted rows)
    float* msk  = (float*)(Vs + 2 * KT * VSTR);   // 2 x [64]

    const int tid = threadIdx.x;
    const int lane = tid & 31, wid = tid >> 5;
    const int g = lane >> 2, t = lane & 3;
    const int qt = (gridDim.x - 1) - blockIdx.x;  // heavy tiles first
    const int bh = blockIdx.y;
    const int b = bh >> 4, h = bh & 15;
    const int q0 = qt * QT;
    const int ktmax = 4 * qt + 3;

    const float* Qp = Qg + ((size_t)bh * NL + q0) * DH;
    const float* Kp = Kg + (size_t)bh * NL * DH;
    const float* Vp = qkv + (size_t)b * NL * ND3 + 2 * ND + h * DH;

    // LDSM base addresses
    const unsigned qs0 = (unsigned)__cvta_generic_to_shared(Qs);
    const unsigned ks0 = (unsigned)__cvta_generic_to_shared(Ks);
    unsigned qb[2], kb4[4];
    {
        const int wq = wid * 32;
#pragma unroll
        for (int mf = 0; mf < 2; mf++) {
            int row = wq + mf * 16 + (lane & 15);
            int col = (lane >> 4) << 2;
            qb[mf] = qs0 + (row * QSTR + col) * 4;
        }
        int krow = (lane & 7) + ((lane & 16) ? 8 : 0);
        int kcol = (lane & 8) ? 4 : 0;
#pragma unroll
        for (int nfp = 0; nfp < 4; nfp++)
            kb4[nfp] = ks0 + ((nfp * 16 + krow) * QSTR + kcol) * 4;
    }
    const unsigned kbufB = KT * QSTR * 4;  // byte offset between K buffers

    // load Q tile (fp32 -> tf32)
    for (int i = tid; i < QT * 16; i += 256) {
        int r = i >> 4, c4 = (i & 15) << 2;
        float4 v = *(const float4*)(Qp + (size_t)r * DH + c4);
        *(uint4*)&Qs[r * QSTR + c4] =
            make_uint4(f2tf(v.x), f2tf(v.y), f2tf(v.z), f2tf(v.w));
    }

    // K/V tile 0 into registers
    const int krow = tid >> 4, kc4 = (tid & 15) << 2;
    // permuted destination rows for V (key j in 8-group -> row j/2 + (j&1)*4)
    int vdst[4];
#pragma unroll
    for (int p = 0; p < 4; p++) {
        int r = krow + p * 16;
        int jj = r & 7;
        vdst[p] = (r & ~7) | ((jj >> 1) | ((jj & 1) << 2));
    }
    float4 kr[4], vr[4];
    float mreg;
#pragma unroll
    for (int p = 0; p < 4; p++) {
        kr[p] = *(const float4*)(Kp + (size_t)(krow + p * 16) * DH + kc4);
        vr[p] = *(const float4*)(Vp + (size_t)(krow + p * 16) * ND3 + kc4);
    }
    mreg = (tid < KT) ? (amask[b * NL + tid] ? 0.f : -1e30f) : 0.f;

    __syncthreads();
#pragma unroll
    for (int p = 0; p < 4; p++) {
        int r = krow + p * 16;
        *(uint4*)&Ks[r * QSTR + kc4] = make_uint4(f2tf(kr[p].x), f2tf(kr[p].y),
                                                  f2tf(kr[p].z), f2tf(kr[p].w));
        *(uint4*)&Vs[vdst[p] * VSTR + kc4] =
            make_uint4(f2tf(vr[p].x), f2tf(vr[p].y),
                       f2tf(vr[p].z), f2tf(vr[p].w));
    }
    if (tid < KT) msk[tid] = mreg;
    __syncthreads();

    float o[2][8][4];
#pragma unroll
    for (int mf = 0; mf < 2; mf++)
#pragma unroll
        for (int nf = 0; nf < 8; nf++)
#pragma unroll
            for (int i = 0; i < 4; i++) o[mf][nf][i] = 0.f;
    float m_st[2][2], l_st[2][2];
#pragma unroll
    for (int mf = 0; mf < 2; mf++) {
        m_st[mf][0] = m_st[mf][1] = -1e30f;
        l_st[mf][0] = l_st[mf][1] = 0.f;
    }

    const int wq = wid * 32;

    for (int kt = 0; kt <= ktmax; kt++) {
        const int buf = kt & 1;
        const unsigned* Vb = Vs + buf * KT * VSTR;
        const float* mb = msk + buf * KT;
        const unsigned kofs = buf * kbufB;
        const bool have_next = (kt < ktmax);

        // prefetch next K/V tile into registers
        if (have_next) {
#pragma unroll
            for (int p = 0; p < 4; p++) {
                size_t rg = (size_t)((kt + 1) * KT + krow + p * 16);
                kr[p] = *(const float4*)(Kp + rg * DH + kc4);
                vr[p] = *(const float4*)(Vp + rg * ND3 + kc4);
            }
            mreg = (tid < KT) ?
                (amask[b * NL + (kt + 1) * KT + tid] ? 0.f : -1e30f) : 0.f;
        }

        // ---- S = Q K^T ----
        float s[2][8][4];
#pragma unroll
        for (int mf = 0; mf < 2; mf++)
#pragma unroll
            for (int nf = 0; nf < 8; nf++)
#pragma unroll
                for (int i = 0; i < 4; i++) s[mf][nf][i] = 0.f;

#pragma unroll
        for (int kc = 0; kc < 8; kc++) {
            const unsigned kadd = kc * 32;  // 8 words
            unsigned a[2][4], bk[4];
            ldsm4(a[0], qb[0] + kadd);
            ldsm4(a[1], qb[1] + kadd);
#pragma unroll
            for (int nfp = 0; nfp < 4; nfp++) {
                ldsm4(bk, kb4[nfp] + kofs + kadd);
                mma8(s[0][2 * nfp],     a[0], bk[0], bk[1]);
                mma8(s[1][2 * nfp],     a[1], bk[0], bk[1]);
                mma8(s[0][2 * nfp + 1], a[0], bk[2], bk[3]);
                mma8(s[1][2 * nfp + 1], a[1], bk[2], bk[3]);
            }
        }

        const bool diag = (kt * KT + KT - 1 > q0);

        // ---- softmax (exp2 domain) ----
#pragma unroll
        for (int mf = 0; mf < 2; mf++) {
            const int rlo = q0 + wq + mf * 16 + g;
            const int rhi = rlo + 8;
#pragma unroll
            for (int nf = 0; nf < 8; nf++) {
                int c = kt * KT + nf * 8 + 2 * t;
                float mk0 = mb[nf * 8 + 2 * t];
                float mk1 = mb[nf * 8 + 2 * t + 1];
                float* sv = s[mf][nf];
                sv[0] = sv[0] * SCL + mk0;
                sv[1] = sv[1] * SCL + mk1;
                sv[2] = sv[2] * SCL + mk0;
                sv[3] = sv[3] * SCL + mk1;
                if (diag) {
                    if (c     > rlo) sv[0] = -1e30f;
                    if (c + 1 > rlo) sv[1] = -1e30f;
                    if (c     > rhi) sv[2] = -1e30f;
                    if (c + 1 > rhi) sv[3] = -1e30f;
                }
            }
            float mx0 = -1e30f, mx1 = -1e30f;
#pragma unroll
            for (int nf = 0; nf < 8; nf++) {
                mx0 = fmaxf(mx0, fmaxf(s[mf][nf][0], s[mf][nf][1]));
                mx1 = fmaxf(mx1, fmaxf(s[mf][nf][2], s[mf][nf][3]));
            }
            mx0 = fmaxf(mx0, __shfl_xor_sync(0xffffffffu, mx0, 1));
            mx0 = fmaxf(mx0, __shfl_xor_sync(0xffffffffu, mx0, 2));
            mx1 = fmaxf(mx1, __shfl_xor_sync(0xffffffffu, mx1, 1));
            mx1 = fmaxf(mx1, __shfl_xor_sync(0xffffffffu, mx1, 2));

            float nm0 = fmaxf(m_st[mf][0], mx0);
            float nm1 = fmaxf(m_st[mf][1], mx1);
            float al0 = exp2f(m_st[mf][0] - nm0);
            float al1 = exp2f(m_st[mf][1] - nm1);
            m_st[mf][0] = nm0; m_st[mf][1] = nm1;

            float sum0 = 0.f, sum1 = 0.f;
#pragma unroll
            for (int nf = 0; nf < 8; nf++) {
                float* sv = s[mf][nf];
                sv[0] = exp2f(sv[0] - nm0); sum0 += sv[0];
                sv[1] = exp2f(sv[1] - nm0); sum0 += sv[1];
                sv[2] = exp2f(sv[2] - nm1); sum1 += sv[2];
                sv[3] = exp2f(sv[3] - nm1); sum1 += sv[3];
            }
            sum0 += __shfl_xor_sync(0xffffffffu, sum0, 1);
            sum0 += __shfl_xor_sync(0xffffffffu, sum0, 2);
            sum1 += __shfl_xor_sync(0xffffffffu, sum1, 1);
            sum1 += __shfl_xor_sync(0xffffffffu, sum1, 2);
            l_st[mf][0] = l_st[mf][0] * al0 + sum0;
            l_st[mf][1] = l_st[mf][1] * al1 + sum1;

#pragma unroll
            for (int nf = 0; nf < 8; nf++) {
                o[mf][nf][0] *= al0; o[mf][nf][1] *= al0;
                o[mf][nf][2] *= al1; o[mf][nf][3] *= al1;
            }
        }

        // ---- O += P V  (P direct from registers; V rows permuted) ----
#pragma unroll
        for (int kc = 0; kc < 8; kc++) {
            const int k0 = kc * 8;
            unsigned pa[2][4];
#pragma unroll
            for (int mf = 0; mf < 2; mf++) {
                pa[mf][0] = f2tf(s[mf][kc][0]);
                pa[mf][1] = f2tf(s[mf][kc][2]);
                pa[mf][2] = f2tf(s[mf][kc][1]);
                pa[mf][3] = f2tf(s[mf][kc][3]);
            }
#pragma unroll
            for (int nf = 0; nf < 8; nf++) {
                unsigned b0 = Vb[(k0 + t) * VSTR + nf * 8 + g];
                unsigned b1 = Vb[(k0 + t + 4) * VSTR + nf * 8 + g];
                mma8(o[0][nf], pa[0], b0, b1);
                mma8(o[1][nf], pa[1], b0, b1);
            }
        }

        // commit next tile to other buffer
        if (have_next) {
            __syncthreads();
            unsigned* Kn = Ks + (buf ^ 1) * KT * QSTR;
            unsigned* Vn = Vs + (buf ^ 1) * KT * VSTR;
#pragma unroll
            for (int p = 0; p < 4; p++) {
                int r = krow + p * 16;
                *(uint4*)&Kn[r * QSTR + kc4] =
                    make_uint4(f2tf(kr[p].x), f2tf(kr[p].y),
                               f2tf(kr[p].z), f2tf(kr[p].w));
                *(uint4*)&Vn[vdst[p] * VSTR + kc4] =
                    make_uint4(f2tf(vr[p].x), f2tf(vr[p].y),
                               f2tf(vr[p].z), f2tf(vr[p].w));
            }
            if (tid < KT) msk[(buf ^ 1) * KT + tid] = mreg;
            __syncthreads();
        }
    }

    // ---- finalize ----
#pragma unroll
    for (int mf = 0; mf < 2; mf++) {
        float inv0 = 1.f / l_st[mf][0];
        float inv1 = 1.f / l_st[mf][1];
        int rlo = q0 + wq + mf * 16 + g;
        float* op = out + ((size_t)b * NL + rlo) * ND + h * DH;
#pragma unroll
        for (int nf = 0; nf < 8; nf++) {
            int col = nf * 8 + 2 * t;
            *(float2*)(op + col) =
                make_float2(o[mf][nf][0] * inv0, o[mf][nf][1] * inv0);
            *(float2*)(op + (size_t)8 * ND + col) =
                make_float2(o[mf][nf][2] * inv1, o[mf][nf][3] * inv1);
        }
    }
}

// ---------------------------------------------------------------------------
extern "C" void kernel_launch(void* const* d_in, const int* in_sizes, int n_in,
                              void* d_out, int out_size)
{
    const float* x     = (const float*)d_in[0];
    const float* Wqkv  = (const float*)d_in[1];
    const float* bqkv  = (const float*)d_in[2];
    const float* Wproj = (const float*)d_in[3];
    const float* bproj = (const float*)d_in[4];
    const int*   amask = (const int*)d_in[5];
    float* out = (float*)d_out;

    float *qkv, *q, *k, *attn;
    cudaGetSymbolAddress((void**)&qkv,  g_qkv);
    cudaGetSymbolAddress((void**)&q,    g_q);
    cudaGetSymbolAddress((void**)&k,    g_k);
    cudaGetSymbolAddress((void**)&attn, g_attn);

    gemm_tf32<<<dim3(ND3 / 128, (NB * NL) / 128), 256>>>(
        x, Wqkv, bqkv, qkv, NB * NL, ND3, ND);

    int total = NB * NL * NH * (DH / 2);
    rope_kernel<<<(total + 255) / 256, 256>>>(qkv, q, k);

    size_t smem = (size_t)(QT * QSTR + 2 * KT * QSTR + 2 * KT * VSTR) * 4
                + 2 * KT * 4;
    cudaFuncSetAttribute(attn_tf32,
                         cudaFuncAttributeMaxDynamicSharedMemorySize,
                         (int)smem);
    attn_tf32<<<dim3(NL / QT, NB * NH), 256, smem>>>(q, k, qkv, amask, attn);

    gemm_tf32<<<dim3(ND / 128, (NB * NL) / 128), 256>>>(
        attn, Wproj, bproj, out, NB * NL, ND, ND);
}